// round 10
// baseline (speedup 1.0000x reference)
#include <cuda_runtime.h>
#include <cstdint>

#define DD 128
#define SASTR 132               // padded A stride in floats (132 mod 32 = 4 banks)
#define MAXM 200000
#define MAXR 256
#define MAXB 8

// -------- scratch (static device memory; no allocs allowed) --------
__device__ float g_Hs[(size_t)MAXM * DD];   // hidden @ Ws^T      (102.4 MB)
__device__ float g_agg[(size_t)MAXM * DD];  // segment_sum output (102.4 MB)
__device__ int   g_deg[MAXM];
__device__ float g_Rr[MAXR * DD];           // rela_embed @ Wr^T
__device__ float g_Qq[MAXB * DD];           // query @ Wqr^T + b
__device__ float g_Wf[DD * DD];             // (mlp2 @ mlp1)^T   -- stored [k][n]
__device__ float g_bf[DD];                  // mlp2 @ b1 + b2
__device__ float g_WsT[DD * DD];            // Ws_attn_w^T       -- stored [k][n]

// -------- packed f32x2 helpers (sm_103a FFMA2 pipe: 2 FMA / instr) --------
__device__ __forceinline__ unsigned long long pack2(float lo, float hi) {
    unsigned long long r;
    asm("mov.b64 %0, {%1,%2};" : "=l"(r) : "f"(lo), "f"(hi));
    return r;
}
__device__ __forceinline__ void fma2(unsigned long long& acc, unsigned long long a, unsigned long long b) {
    asm("fma.rn.f32x2 %0, %1, %2, %0;" : "+l"(acc) : "l"(a), "l"(b));
}
__device__ __forceinline__ float2 unpack2(unsigned long long v) {
    float lo, hi;
    asm("mov.b64 {%0,%1}, %2;" : "=f"(lo), "=f"(hi) : "l"(v));
    return make_float2(lo, hi);
}

// -------- tiny precompute: WfT, bf, Rr, Qq, WsT --------
__global__ void prep_kernel(const float* __restrict__ mlp1_w, const float* __restrict__ mlp1_b,
                            const float* __restrict__ mlp2_w, const float* __restrict__ mlp2_b,
                            const float* __restrict__ rela,   const float* __restrict__ Wr,
                            const float* __restrict__ query,  const float* __restrict__ Wqr,
                            const float* __restrict__ Wqr_b,  const float* __restrict__ Ws,
                            int R, int B)
{
    int t = threadIdx.x;
    int bx = blockIdx.x;
    if (bx < DD) {
        int i = bx;                           // output dim (n) of fused weight
        float acc = 0.f;
        for (int j = 0; j < DD; j++) acc += mlp2_w[i * DD + j] * mlp1_w[j * DD + t];
        g_Wf[t * DD + i] = acc;               // store TRANSPOSED: [k][n]
        __shared__ float s[DD];
        s[t] = mlp2_w[i * DD + t] * mlp1_b[t];
        __syncthreads();
        if (t == 0) {
            float b = 0.f;
            for (int j = 0; j < DD; j++) b += s[j];
            g_bf[i] = b + mlp2_b[i];
        }
    } else if (bx < 2 * DD) {
        int n = bx - DD;                      // transpose Ws: g_WsT[k][n] = Ws[n][k]
        g_WsT[t * DD + n] = Ws[n * DD + t];
    } else if (bx < 2 * DD + R) {
        int r = bx - 2 * DD;                  // Rr[r][t] = rela[r]·Wr[t]
        float acc = 0.f;
        for (int d = 0; d < DD; d++) acc += rela[r * DD + d] * Wr[t * DD + d];
        g_Rr[r * DD + t] = acc;
    } else {
        int b = bx - 2 * DD - R;              // Qq[b][t] = query[b]·Wqr[t] + b[t]
        float acc = Wqr_b[t];
        for (int d = 0; d < DD; d++) acc += query[b * DD + d] * Wqr[t * DD + d];
        g_Qq[b * DD + t] = acc;
    }
}

// -------- GEMM: C[M,128] = epi(A[M,128] @ WT[128,128]) --------
// WT pre-transposed [k][n]. Tile BM=128 x BN=64, 256 threads, thread tile 8x4.
// sA padded to stride 132; thread rows interleaved (ty + 16*i) so the warp's
// two A-addresses land on disjoint banks -> conflict-free A broadcasts.
// smem = 128*132*4 + 128*64*4 = 100,352 B -> 2 CTAs/SM.
// mode 0: plain.  mode 1: relu(x + bias[n]), zeroed where deg[row]==0.
__global__ __launch_bounds__(256, 2)
void gemm128_kernel(const float* __restrict__ A, const float* __restrict__ WT,
                    const float* __restrict__ bias, const int* __restrict__ deg,
                    float* __restrict__ C, int M, int mode)
{
    extern __shared__ float smem[];
    float* sA = smem;                       // 128(m) x 132(padded k-stride)
    float* sW = smem + 128 * SASTR;         // 128(k) x 64(n half)

    const int tid = threadIdx.x;
    const int mb = blockIdx.x >> 1;
    const int nb = blockIdx.x & 1;
    const int m0 = mb * 128;
    const int n0 = nb * 64;

    const float4* A4 = reinterpret_cast<const float4*>(A);
    float4* sA4 = reinterpret_cast<float4*>(sA);
    #pragma unroll
    for (int i = tid; i < DD * DD / 4; i += 256) {
        int row = i >> 5;
        int gr = m0 + row;
        float4 v = make_float4(0.f, 0.f, 0.f, 0.f);
        if (gr < M) v = A4[(size_t)gr * 32 + (i & 31)];
        sA4[row * (SASTR / 4) + (i & 31)] = v;
    }
    const float4* W4 = reinterpret_cast<const float4*>(WT);
    float4* sW4 = reinterpret_cast<float4*>(sW);
    #pragma unroll
    for (int i = tid; i < DD * 64 / 4; i += 256) {
        int row = i >> 4;
        sW4[i] = W4[row * 32 + nb * 16 + (i & 15)];
    }
    __syncthreads();

    const int tx = tid & 15;        // col group: 4 cols (n) at n0 + tx*4
    const int ty = tid >> 4;        // row base: rows ty + 16*i, i=0..7
    const float* sAr = sA + ty * SASTR;
    const float* sWc = sW + tx * 4;

    unsigned long long acc[8][2];
    #pragma unroll
    for (int i = 0; i < 8; i++) { acc[i][0] = 0ULL; acc[i][1] = 0ULL; }

    #pragma unroll 2
    for (int k = 0; k < DD; k += 4) {
        // 8 A-loads along k; warp's two addrs differ by 1 row (4 banks) -> 1 wf each
        float4 a4[8];
        #pragma unroll
        for (int i = 0; i < 8; i++)
            a4[i] = *reinterpret_cast<const float4*>(sAr + i * 16 * SASTR + k);
        // 4 W-loads (one per k-step; 16 distinct addrs x 16B = 2 wf each)
        ulonglong2 w[4];
        #pragma unroll
        for (int kk = 0; kk < 4; kk++)
            w[kk] = *reinterpret_cast<const ulonglong2*>(sWc + (size_t)(k + kk) * 64);
        // 64 fma2 (128 FMA) per chunk
        #pragma unroll
        for (int kk = 0; kk < 4; kk++) {
            #pragma unroll
            for (int i = 0; i < 8; i++) {
                float a = (&a4[i].x)[kk];
                unsigned long long ad = pack2(a, a);
                fma2(acc[i][0], ad, w[kk].x);
                fma2(acc[i][1], ad, w[kk].y);
            }
        }
    }

    #pragma unroll
    for (int i = 0; i < 8; i++) {
        int row = m0 + ty + 16 * i;
        if (row >= M) continue;
        float out[4];
        float2 v0 = unpack2(acc[i][0]);
        float2 v1 = unpack2(acc[i][1]);
        out[0] = v0.x; out[1] = v0.y; out[2] = v1.x; out[3] = v1.y;
        if (mode == 1) {
            bool keep = deg[row] > 0;
            #pragma unroll
            for (int j = 0; j < 4; j++) {
                float x = fmaxf(out[j] + bias[n0 + tx * 4 + j], 0.f);
                out[j] = keep ? x : 0.f;
            }
        }
        *reinterpret_cast<float4*>(C + (size_t)row * DD + n0 + tx * 4) =
            make_float4(out[0], out[1], out[2], out[3]);
    }
}

// -------- edge kernel: TWO edges per warp (MLP: 10 outstanding gathers) --------
// alpha = sigmoid( W_attn · relu(Hs[sub] + Rr[rel] + Qq[bat]) )
// agg[obj] += hidden[sub] * rela[rel] * alpha   (vector red.global)
__global__ __launch_bounds__(256)
void edge_kernel(const int4* __restrict__ edges, const float* __restrict__ Wattn,
                 const float* __restrict__ hidden, const float* __restrict__ rela, int E)
{
    const int base = blockIdx.x * 16 + ((threadIdx.x >> 5) << 1);
    const int lane = threadIdx.x & 31;
    const int c = lane * 4;
    const bool v0 = base < E;
    const bool v1 = base + 1 < E;
    const int4 ed0 = v0 ? edges[base]     : make_int4(0, 0, 0, 0);
    const int4 ed1 = v1 ? edges[base + 1] : make_int4(0, 0, 0, 0);

    float4 hs0 = *reinterpret_cast<const float4*>(g_Hs + (size_t)ed0.y * DD + c);
    float4 hs1 = *reinterpret_cast<const float4*>(g_Hs + (size_t)ed1.y * DD + c);
    float4 mh0 = *reinterpret_cast<const float4*>(hidden + (size_t)ed0.y * DD + c);
    float4 mh1 = *reinterpret_cast<const float4*>(hidden + (size_t)ed1.y * DD + c);
    float4 rr0 = *reinterpret_cast<const float4*>(g_Rr + (size_t)ed0.z * DD + c);
    float4 rr1 = *reinterpret_cast<const float4*>(g_Rr + (size_t)ed1.z * DD + c);
    float4 mr0 = *reinterpret_cast<const float4*>(rela + (size_t)ed0.z * DD + c);
    float4 mr1 = *reinterpret_cast<const float4*>(rela + (size_t)ed1.z * DD + c);
    float4 qq0 = *reinterpret_cast<const float4*>(g_Qq + (size_t)ed0.x * DD + c);
    float4 qq1 = *reinterpret_cast<const float4*>(g_Qq + (size_t)ed1.x * DD + c);
    float4 wa  = *reinterpret_cast<const float4*>(Wattn + c);

    float p0 = fmaxf(hs0.x + rr0.x + qq0.x, 0.f) * wa.x
             + fmaxf(hs0.y + rr0.y + qq0.y, 0.f) * wa.y
             + fmaxf(hs0.z + rr0.z + qq0.z, 0.f) * wa.z
             + fmaxf(hs0.w + rr0.w + qq0.w, 0.f) * wa.w;
    float p1 = fmaxf(hs1.x + rr1.x + qq1.x, 0.f) * wa.x
             + fmaxf(hs1.y + rr1.y + qq1.y, 0.f) * wa.y
             + fmaxf(hs1.z + rr1.z + qq1.z, 0.f) * wa.z
             + fmaxf(hs1.w + rr1.w + qq1.w, 0.f) * wa.w;
    #pragma unroll
    for (int o = 16; o > 0; o >>= 1) {
        p0 += __shfl_xor_sync(0xffffffffu, p0, o);
        p1 += __shfl_xor_sync(0xffffffffu, p1, o);
    }
    float alpha0 = 1.f / (1.f + __expf(-p0));
    float alpha1 = 1.f / (1.f + __expf(-p1));

    if (v0) {
        float* dst = g_agg + (size_t)ed0.w * DD + c;
        asm volatile("red.global.add.v4.f32 [%0], {%1,%2,%3,%4};"
                     :: "l"(dst),
                        "f"(mh0.x * mr0.x * alpha0), "f"(mh0.y * mr0.y * alpha0),
                        "f"(mh0.z * mr0.z * alpha0), "f"(mh0.w * mr0.w * alpha0) : "memory");
        if (lane == 0) atomicAdd(&g_deg[ed0.w], 1);
    }
    if (v1) {
        float* dst = g_agg + (size_t)ed1.w * DD + c;
        asm volatile("red.global.add.v4.f32 [%0], {%1,%2,%3,%4};"
                     :: "l"(dst),
                        "f"(mh1.x * mr1.x * alpha1), "f"(mh1.y * mr1.y * alpha1),
                        "f"(mh1.z * mr1.z * alpha1), "f"(mh1.w * mr1.w * alpha1) : "memory");
        if (lane == 0) atomicAdd(&g_deg[ed1.w], 1);
    }
}

// -------- launch --------
extern "C" void kernel_launch(void* const* d_in, const int* in_sizes, int n_in,
                              void* d_out, int out_size)
{
    const float* query  = (const float*)d_in[0];
    const float* hidden = (const float*)d_in[3];
    const int*   edges  = (const int*)d_in[4];
    const float* Ws     = (const float*)d_in[6];
    const float* Wr     = (const float*)d_in[7];
    const float* Wqr    = (const float*)d_in[8];
    const float* Wqr_b  = (const float*)d_in[9];
    const float* Wattn  = (const float*)d_in[10];
    const float* rela   = (const float*)d_in[11];
    const float* mlp1_w = (const float*)d_in[12];
    const float* mlp1_b = (const float*)d_in[13];
    const float* mlp2_w = (const float*)d_in[14];
    const float* mlp2_b = (const float*)d_in[15];

    int M = in_sizes[3] / DD;     // B*N = 200000
    int E = in_sizes[4] / 4;      // 600000
    int R = in_sizes[11] / DD;    // 200
    int B = in_sizes[0] / DD;     // 4

    void *aggp = 0, *degp = 0, *hsp = 0, *wfp = 0, *bfp = 0, *wstp = 0;
    cudaGetSymbolAddress(&aggp, g_agg);
    cudaGetSymbolAddress(&degp, g_deg);
    cudaGetSymbolAddress(&hsp,  g_Hs);
    cudaGetSymbolAddress(&wfp,  g_Wf);
    cudaGetSymbolAddress(&bfp,  g_bf);
    cudaGetSymbolAddress(&wstp, g_WsT);

    cudaMemsetAsync(aggp, 0, (size_t)M * DD * sizeof(float), 0);
    cudaMemsetAsync(degp, 0, (size_t)M * sizeof(int), 0);

    prep_kernel<<<2 * DD + R + B, DD>>>(mlp1_w, mlp1_b, mlp2_w, mlp2_b,
                                        rela, Wr, query, Wqr, Wqr_b, Ws, R, B);

    size_t smem = (size_t)(128 * SASTR + DD * 64) * sizeof(float);   // 100,352 B
    cudaFuncSetAttribute(gemm128_kernel, cudaFuncAttributeMaxDynamicSharedMemorySize, (int)smem);

    int grid = ((M + 127) / 128) * 2;    // x2 for the two N-halves

    // Hs = hidden @ Ws^T
    gemm128_kernel<<<grid, 256, smem>>>(hidden, (const float*)wstp, nullptr, nullptr,
                                        (float*)hsp, M, 0);
    // per-edge attention + scatter (2 edges per warp, 16 per block)
    edge_kernel<<<(E + 15) / 16, 256>>>((const int4*)edges, Wattn, hidden, rela, E);

    // out = mask(deg>0) * relu(agg @ (mlp2·mlp1)^T + b')
    gemm128_kernel<<<grid, 256, smem>>>((const float*)aggp, (const float*)wfp,
                                        (const float*)bfp, (const int*)degp,
                                        (float*)d_out, M, 1);
}

// round 11
// speedup vs baseline: 1.6711x; 1.6711x over previous
#include <cuda_runtime.h>
#include <cuda_fp16.h>
#include <cstdint>

#define DD 128
#define HSTR 136                 // smem half-row stride (136 halves = 272B ≡ 4 banks)
#define MAXM 200000
#define MAXR 256
#define MAXB 8

// -------- scratch (static device memory; no allocs allowed) --------
__device__ __half g_HsH[(size_t)MAXM * DD]; // hidden @ Ws^T in fp16 (51.2 MB)
__device__ float  g_agg[(size_t)MAXM * DD]; // segment_sum output (102.4 MB)
__device__ int    g_deg[MAXM];              // receive flags
__device__ float  g_Rr[MAXR * DD];          // rela_embed @ Wr^T
__device__ float  g_Qq[MAXB * DD];          // query @ Wqr^T + b
__device__ float  g_Wf[DD * DD];            // mlp2 @ mlp1, natural [n][k]
__device__ float  g_bf[DD];                 // mlp2 @ b1 + b2
__device__ __half g_WsH[DD * DD];           // fp16(Ws_attn_w) [n][k]
__device__ __half g_WfH[DD * DD];           // fp16 hi part of Wf [n][k]
__device__ __half g_WfL[DD * DD];           // fp16 lo part of Wf [n][k]

__device__ __forceinline__ uint32_t h2u(__half2 h) {
    return *reinterpret_cast<uint32_t*>(&h);
}

// m16n8k16 f16 MMA, f32 accum (baseline PTX sm_80+)
__device__ __forceinline__ void mma16816(float* d, const uint32_t* a, uint32_t b0, uint32_t b1) {
    asm volatile(
        "mma.sync.aligned.m16n8k16.row.col.f32.f16.f16.f32 "
        "{%0,%1,%2,%3}, {%4,%5,%6,%7}, {%8,%9}, {%0,%1,%2,%3};"
        : "+f"(d[0]), "+f"(d[1]), "+f"(d[2]), "+f"(d[3])
        : "r"(a[0]), "r"(a[1]), "r"(a[2]), "r"(a[3]), "r"(b0), "r"(b1));
}

// ================= prep: Wf (natural [n][k]), bf, Rr, Qq =================
__global__ void prep_kernel(const float* __restrict__ mlp1_w, const float* __restrict__ mlp1_b,
                            const float* __restrict__ mlp2_w, const float* __restrict__ mlp2_b,
                            const float* __restrict__ rela,   const float* __restrict__ Wr,
                            const float* __restrict__ query,  const float* __restrict__ Wqr,
                            const float* __restrict__ Wqr_b,  int R)
{
    int t = threadIdx.x;
    int bx = blockIdx.x;
    if (bx < DD) {
        int i = bx;
        float acc = 0.f;
        for (int j = 0; j < DD; j++) acc += mlp2_w[i * DD + j] * mlp1_w[j * DD + t];
        g_Wf[i * DD + t] = acc;
        __shared__ float s[DD];
        s[t] = mlp2_w[i * DD + t] * mlp1_b[t];
        __syncthreads();
        if (t == 0) {
            float b = 0.f;
            for (int j = 0; j < DD; j++) b += s[j];
            g_bf[i] = b + mlp2_b[i];
        }
    } else if (bx < DD + R) {
        int r = bx - DD;
        float acc = 0.f;
        for (int d = 0; d < DD; d++) acc += rela[r * DD + d] * Wr[t * DD + d];
        g_Rr[r * DD + t] = acc;
    } else {
        int b = bx - DD - R;
        float acc = Wqr_b[t];
        for (int d = 0; d < DD; d++) acc += query[b * DD + d] * Wqr[t * DD + d];
        g_Qq[b * DD + t] = acc;
    }
}

// convert Ws -> fp16; Wf -> fp16 hi/lo split
__global__ void convert_kernel(const float* __restrict__ Ws) {
    int i = blockIdx.x * 256 + threadIdx.x;
    if (i >= DD * DD) return;
    g_WsH[i] = __float2half_rn(Ws[i]);
    float w = g_Wf[i];
    __half h = __float2half_rn(w);
    g_WfH[i] = h;
    g_WfL[i] = __float2half_rn(w - __half2float(h));
}

// ================= GEMM1: Hs(fp16) = hidden(fp32) @ Ws^T via fp16 MMA =================
// CTA 256 thr / 8 warps, tile 128m x 64n (nb splits the 128 n-dim).
// Warp grid 4m x 2n; warp tile 32m x 32n = 2 mtiles x 4 ntiles of m16n8k16; 8 k-steps.
#define SM1_BYTES ((128 + 64) * HSTR * 2)   // 52,224 B
__global__ __launch_bounds__(256, 2)
void gemm_h1(const float* __restrict__ A, const __half* __restrict__ W,
             __half* __restrict__ C, int M)
{
    extern __shared__ __half smh[];
    __half* sA = smh;                  // 128 x HSTR
    __half* sW = smh + 128 * HSTR;     // 64 x HSTR

    const int tid = threadIdx.x;
    const int mb = blockIdx.x >> 1;
    const int nb = blockIdx.x & 1;
    const int m0 = mb * 128;
    const int n0 = nb * 64;

    const float4* A4 = reinterpret_cast<const float4*>(A);
    #pragma unroll
    for (int i = tid; i < 128 * 32; i += 256) {
        int row = i >> 5, c4 = i & 31;
        int gr = m0 + row;
        float4 v = make_float4(0.f, 0.f, 0.f, 0.f);
        if (gr < M) v = A4[(size_t)gr * 32 + c4];
        uint2 u = make_uint2(h2u(__floats2half2_rn(v.x, v.y)),
                             h2u(__floats2half2_rn(v.z, v.w)));
        *reinterpret_cast<uint2*>(&sA[row * HSTR + c4 * 4]) = u;
    }
    const uint4* W4 = reinterpret_cast<const uint4*>(W);
    #pragma unroll
    for (int i = tid; i < 64 * 16; i += 256) {
        int row = i >> 4, c8 = i & 15;
        *reinterpret_cast<uint4*>(&sW[row * HSTR + c8 * 8]) = W4[(size_t)(n0 + row) * 16 + c8];
    }
    __syncthreads();

    const int lane = tid & 31;
    const int wid = tid >> 5;
    const int g = lane >> 2;
    const int t4 = lane & 3;
    const int wm = (wid >> 1) * 32;
    const int wn = (wid & 1) * 32;

    const __half* aB = sA + (wm + g) * HSTR;
    const __half* bB = sW + (wn + g) * HSTR;

    float acc[2][4][4];
    #pragma unroll
    for (int mt = 0; mt < 2; mt++)
        #pragma unroll
        for (int nt = 0; nt < 4; nt++)
            #pragma unroll
            for (int q = 0; q < 4; q++) acc[mt][nt][q] = 0.f;

    #pragma unroll
    for (int ks = 0; ks < 8; ks++) {
        const int k0 = ks * 16;
        uint32_t a[2][4];
        #pragma unroll
        for (int mt = 0; mt < 2; mt++) {
            const __half* b = aB + mt * 16 * HSTR;
            a[mt][0] = *reinterpret_cast<const uint32_t*>(&b[k0 + 2 * t4]);
            a[mt][1] = *reinterpret_cast<const uint32_t*>(&b[8 * HSTR + k0 + 2 * t4]);
            a[mt][2] = *reinterpret_cast<const uint32_t*>(&b[k0 + 8 + 2 * t4]);
            a[mt][3] = *reinterpret_cast<const uint32_t*>(&b[8 * HSTR + k0 + 8 + 2 * t4]);
        }
        #pragma unroll
        for (int nt = 0; nt < 4; nt++) {
            const __half* bp = bB + nt * 8 * HSTR;
            uint32_t b0 = *reinterpret_cast<const uint32_t*>(&bp[k0 + 2 * t4]);
            uint32_t b1 = *reinterpret_cast<const uint32_t*>(&bp[k0 + 8 + 2 * t4]);
            mma16816(acc[0][nt], a[0], b0, b1);
            mma16816(acc[1][nt], a[1], b0, b1);
        }
    }

    #pragma unroll
    for (int mt = 0; mt < 2; mt++) {
        int r0 = m0 + wm + mt * 16 + g;
        int r1 = r0 + 8;
        #pragma unroll
        for (int nt = 0; nt < 4; nt++) {
            int col = n0 + wn + nt * 8 + 2 * t4;
            if (r0 < M)
                *reinterpret_cast<uint32_t*>(&C[(size_t)r0 * DD + col]) =
                    h2u(__floats2half2_rn(acc[mt][nt][0], acc[mt][nt][1]));
            if (r1 < M)
                *reinterpret_cast<uint32_t*>(&C[(size_t)r1 * DD + col]) =
                    h2u(__floats2half2_rn(acc[mt][nt][2], acc[mt][nt][3]));
        }
    }
}

// ================= GEMM2: out(fp32) = mask*relu(agg @ Wf^T + bf), W fp16 hi/lo x2 =================
#define SM2_BYTES ((128 + 128) * HSTR * 2)  // 69,632 B
__global__ __launch_bounds__(256, 2)
void gemm_h2(const float* __restrict__ A, const __half* __restrict__ Wh,
             const __half* __restrict__ Wl, const float* __restrict__ bias,
             const int* __restrict__ deg, float* __restrict__ C, int M)
{
    extern __shared__ __half smh[];
    __half* sA  = smh;                  // 128 x HSTR
    __half* sWh = smh + 128 * HSTR;     // 64 x HSTR
    __half* sWl = smh + 192 * HSTR;     // 64 x HSTR

    const int tid = threadIdx.x;
    const int mb = blockIdx.x >> 1;
    const int nb = blockIdx.x & 1;
    const int m0 = mb * 128;
    const int n0 = nb * 64;

    const float4* A4 = reinterpret_cast<const float4*>(A);
    #pragma unroll
    for (int i = tid; i < 128 * 32; i += 256) {
        int row = i >> 5, c4 = i & 31;
        int gr = m0 + row;
        float4 v = make_float4(0.f, 0.f, 0.f, 0.f);
        if (gr < M) v = A4[(size_t)gr * 32 + c4];
        uint2 u = make_uint2(h2u(__floats2half2_rn(v.x, v.y)),
                             h2u(__floats2half2_rn(v.z, v.w)));
        *reinterpret_cast<uint2*>(&sA[row * HSTR + c4 * 4]) = u;
    }
    const uint4* WH4 = reinterpret_cast<const uint4*>(Wh);
    const uint4* WL4 = reinterpret_cast<const uint4*>(Wl);
    #pragma unroll
    for (int i = tid; i < 64 * 16; i += 256) {
        int row = i >> 4, c8 = i & 15;
        *reinterpret_cast<uint4*>(&sWh[row * HSTR + c8 * 8]) = WH4[(size_t)(n0 + row) * 16 + c8];
        *reinterpret_cast<uint4*>(&sWl[row * HSTR + c8 * 8]) = WL4[(size_t)(n0 + row) * 16 + c8];
    }
    __syncthreads();

    const int lane = tid & 31;
    const int wid = tid >> 5;
    const int g = lane >> 2;
    const int t4 = lane & 3;
    const int wm = (wid >> 1) * 32;
    const int wn = (wid & 1) * 32;

    const __half* aB  = sA  + (wm + g) * HSTR;
    const __half* bhB = sWh + (wn + g) * HSTR;
    const __half* blB = sWl + (wn + g) * HSTR;

    float acc[2][4][4];
    #pragma unroll
    for (int mt = 0; mt < 2; mt++)
        #pragma unroll
        for (int nt = 0; nt < 4; nt++)
            #pragma unroll
            for (int q = 0; q < 4; q++) acc[mt][nt][q] = 0.f;

    #pragma unroll
    for (int ks = 0; ks < 8; ks++) {
        const int k0 = ks * 16;
        uint32_t a[2][4];
        #pragma unroll
        for (int mt = 0; mt < 2; mt++) {
            const __half* b = aB + mt * 16 * HSTR;
            a[mt][0] = *reinterpret_cast<const uint32_t*>(&b[k0 + 2 * t4]);
            a[mt][1] = *reinterpret_cast<const uint32_t*>(&b[8 * HSTR + k0 + 2 * t4]);
            a[mt][2] = *reinterpret_cast<const uint32_t*>(&b[k0 + 8 + 2 * t4]);
            a[mt][3] = *reinterpret_cast<const uint32_t*>(&b[8 * HSTR + k0 + 8 + 2 * t4]);
        }
        #pragma unroll
        for (int nt = 0; nt < 4; nt++) {
            const __half* bh = bhB + nt * 8 * HSTR;
            const __half* bl = blB + nt * 8 * HSTR;
            uint32_t bh0 = *reinterpret_cast<const uint32_t*>(&bh[k0 + 2 * t4]);
            uint32_t bh1 = *reinterpret_cast<const uint32_t*>(&bh[k0 + 8 + 2 * t4]);
            uint32_t bl0 = *reinterpret_cast<const uint32_t*>(&bl[k0 + 2 * t4]);
            uint32_t bl1 = *reinterpret_cast<const uint32_t*>(&bl[k0 + 8 + 2 * t4]);
            #pragma unroll
            for (int mt = 0; mt < 2; mt++) {
                mma16816(acc[mt][nt], a[mt], bh0, bh1);
                mma16816(acc[mt][nt], a[mt], bl0, bl1);
            }
        }
    }

    #pragma unroll
    for (int mt = 0; mt < 2; mt++) {
        int r0 = m0 + wm + mt * 16 + g;
        int r1 = r0 + 8;
        bool k0ok = r0 < M, k1ok = r1 < M;
        bool keep0 = k0ok && deg[r0] > 0;
        bool keep1 = k1ok && deg[r1] > 0;
        #pragma unroll
        for (int nt = 0; nt < 4; nt++) {
            int col = n0 + wn + nt * 8 + 2 * t4;
            float b0 = bias[col], b1 = bias[col + 1];
            float c0 = keep0 ? fmaxf(acc[mt][nt][0] + b0, 0.f) : 0.f;
            float c1 = keep0 ? fmaxf(acc[mt][nt][1] + b1, 0.f) : 0.f;
            float c2 = keep1 ? fmaxf(acc[mt][nt][2] + b0, 0.f) : 0.f;
            float c3 = keep1 ? fmaxf(acc[mt][nt][3] + b1, 0.f) : 0.f;
            if (k0ok) *reinterpret_cast<float2*>(C + (size_t)r0 * DD + col) = make_float2(c0, c1);
            if (k1ok) *reinterpret_cast<float2*>(C + (size_t)r1 * DD + col) = make_float2(c2, c3);
        }
    }
}

// -------- edge kernel: 2 edges/warp; Hs gathered in fp16 --------
__global__ __launch_bounds__(256)
void edge_kernel(const int4* __restrict__ edges, const float* __restrict__ Wattn,
                 const float* __restrict__ hidden, const float* __restrict__ rela, int E)
{
    const int base = blockIdx.x * 16 + ((threadIdx.x >> 5) << 1);
    const int lane = threadIdx.x & 31;
    const int c = lane * 4;
    const bool v0 = base < E;
    const bool v1 = base + 1 < E;
    const int4 ed0 = v0 ? edges[base]     : make_int4(0, 0, 0, 0);
    const int4 ed1 = v1 ? edges[base + 1] : make_int4(0, 0, 0, 0);

    uint2 hu0 = *reinterpret_cast<const uint2*>(g_HsH + (size_t)ed0.y * DD + c);
    uint2 hu1 = *reinterpret_cast<const uint2*>(g_HsH + (size_t)ed1.y * DD + c);
    float4 mh0 = *reinterpret_cast<const float4*>(hidden + (size_t)ed0.y * DD + c);
    float4 mh1 = *reinterpret_cast<const float4*>(hidden + (size_t)ed1.y * DD + c);
    float4 rr0 = *reinterpret_cast<const float4*>(g_Rr + (size_t)ed0.z * DD + c);
    float4 rr1 = *reinterpret_cast<const float4*>(g_Rr + (size_t)ed1.z * DD + c);
    float4 mr0 = *reinterpret_cast<const float4*>(rela + (size_t)ed0.z * DD + c);
    float4 mr1 = *reinterpret_cast<const float4*>(rela + (size_t)ed1.z * DD + c);
    float4 qq0 = *reinterpret_cast<const float4*>(g_Qq + (size_t)ed0.x * DD + c);
    float4 qq1 = *reinterpret_cast<const float4*>(g_Qq + (size_t)ed1.x * DD + c);
    float4 wa  = *reinterpret_cast<const float4*>(Wattn + c);

    float2 h0a = __half22float2(*reinterpret_cast<const __half2*>(&hu0.x));
    float2 h0b = __half22float2(*reinterpret_cast<const __half2*>(&hu0.y));
    float2 h1a = __half22float2(*reinterpret_cast<const __half2*>(&hu1.x));
    float2 h1b = __half22float2(*reinterpret_cast<const __half2*>(&hu1.y));

    float p0 = fmaxf(h0a.x + rr0.x + qq0.x, 0.f) * wa.x
             + fmaxf(h0a.y + rr0.y + qq0.y, 0.f) * wa.y
             + fmaxf(h0b.x + rr0.z + qq0.z, 0.f) * wa.z
             + fmaxf(h0b.y + rr0.w + qq0.w, 0.f) * wa.w;
    float p1 = fmaxf(h1a.x + rr1.x + qq1.x, 0.f) * wa.x
             + fmaxf(h1a.y + rr1.y + qq1.y, 0.f) * wa.y
             + fmaxf(h1b.x + rr1.z + qq1.z, 0.f) * wa.z
             + fmaxf(h1b.y + rr1.w + qq1.w, 0.f) * wa.w;
    #pragma unroll
    for (int o = 16; o > 0; o >>= 1) {
        p0 += __shfl_xor_sync(0xffffffffu, p0, o);
        p1 += __shfl_xor_sync(0xffffffffu, p1, o);
    }
    float alpha0 = 1.f / (1.f + __expf(-p0));
    float alpha1 = 1.f / (1.f + __expf(-p1));

    if (v0) {
        float* dst = g_agg + (size_t)ed0.w * DD + c;
        asm volatile("red.global.add.v4.f32 [%0], {%1,%2,%3,%4};"
                     :: "l"(dst),
                        "f"(mh0.x * mr0.x * alpha0), "f"(mh0.y * mr0.y * alpha0),
                        "f"(mh0.z * mr0.z * alpha0), "f"(mh0.w * mr0.w * alpha0) : "memory");
        if (lane == 0) g_deg[ed0.w] = 1;
    }
    if (v1) {
        float* dst = g_agg + (size_t)ed1.w * DD + c;
        asm volatile("red.global.add.v4.f32 [%0], {%1,%2,%3,%4};"
                     :: "l"(dst),
                        "f"(mh1.x * mr1.x * alpha1), "f"(mh1.y * mr1.y * alpha1),
                        "f"(mh1.z * mr1.z * alpha1), "f"(mh1.w * mr1.w * alpha1) : "memory");
        if (lane == 0) g_deg[ed1.w] = 1;
    }
}

// -------- launch --------
extern "C" void kernel_launch(void* const* d_in, const int* in_sizes, int n_in,
                              void* d_out, int out_size)
{
    const float* query  = (const float*)d_in[0];
    const float* hidden = (const float*)d_in[3];
    const int*   edges  = (const int*)d_in[4];
    const float* Ws     = (const float*)d_in[6];
    const float* Wr     = (const float*)d_in[7];
    const float* Wqr    = (const float*)d_in[8];
    const float* Wqr_b  = (const float*)d_in[9];
    const float* Wattn  = (const float*)d_in[10];
    const float* rela   = (const float*)d_in[11];
    const float* mlp1_w = (const float*)d_in[12];
    const float* mlp1_b = (const float*)d_in[13];
    const float* mlp2_w = (const float*)d_in[14];
    const float* mlp2_b = (const float*)d_in[15];

    int M = in_sizes[3] / DD;     // B*N = 200000
    int E = in_sizes[4] / 4;      // 600000
    int R = in_sizes[11] / DD;    // 200
    int B = in_sizes[0] / DD;     // 4

    void *aggp = 0, *degp = 0, *hshp = 0, *bfp = 0, *wshp = 0, *wfhp = 0, *wflp = 0;
    cudaGetSymbolAddress(&aggp, g_agg);
    cudaGetSymbolAddress(&degp, g_deg);
    cudaGetSymbolAddress(&hshp, g_HsH);
    cudaGetSymbolAddress(&bfp,  g_bf);
    cudaGetSymbolAddress(&wshp, g_WsH);
    cudaGetSymbolAddress(&wfhp, g_WfH);
    cudaGetSymbolAddress(&wflp, g_WfL);

    cudaMemsetAsync(aggp, 0, (size_t)M * DD * sizeof(float), 0);
    cudaMemsetAsync(degp, 0, (size_t)M * sizeof(int), 0);

    prep_kernel<<<DD + R + B, DD>>>(mlp1_w, mlp1_b, mlp2_w, mlp2_b,
                                    rela, Wr, query, Wqr, Wqr_b, R);
    convert_kernel<<<(DD * DD + 255) / 256, 256>>>(Ws);

    cudaFuncSetAttribute(gemm_h1, cudaFuncAttributeMaxDynamicSharedMemorySize, SM1_BYTES);
    cudaFuncSetAttribute(gemm_h2, cudaFuncAttributeMaxDynamicSharedMemorySize, SM2_BYTES);
    int grid = ((M + 127) / 128) * 2;

    // Hs(fp16) = hidden @ Ws^T
    gemm_h1<<<grid, 256, SM1_BYTES>>>(hidden, (const __half*)wshp, (__half*)hshp, M);
    // per-edge attention + scatter
    edge_kernel<<<(E + 15) / 16, 256>>>((const int4*)edges, Wattn, hidden, rela, E);
    // out = mask(deg) * relu(agg @ Wf^T + bf)   (Wf split hi/lo fp16)
    gemm_h2<<<grid, 256, SM2_BYTES>>>((const float*)aggp, (const __half*)wfhp,
                                      (const __half*)wflp, (const float*)bfp,
                                      (const int*)degp, (float*)d_out, M);
}